// round 16
// baseline (speedup 1.0000x reference)
#include <cuda_runtime.h>
#include <math.h>

#define B_    16
#define T_    4
#define CIN_  128
#define COUT_ 128
#define H_    56
#define W_    56
#define HW_   (H_*W_)

#define CT    64     // couts per block
#define CPT   4      // couts per thread
#define PX    4      // pixels per thread
#define RPT   2      // output rows per thread (share weight loads)
#define NTHREADS 224 // cg = tid&15 (16 cout-groups), wg = tid>>4 (14 width-groups)
#define NCTAS (28*2*16)                // 896
#define MSLOTS (RPT*CPT*PX)            // 32 membrane slots per thread

// dynamic smem: s_in[2][128][60] — 2-slot ring of staged input rows
// idx k holds input col (k-1): cols -1..56 at 0..57
#define SROW   60
#define SMEM_BYTES (2*CIN_*SROW*4)     // 61440 -> 3 CTAs/SM

typedef unsigned long long u64;

// transposed weights: wT[kh][kw][ci][co]
__device__ float g_wT[9*CIN_*COUT_];
// membrane scratch: [cta][slot][tid] — coalesced per slot, L2-resident
__device__ float g_mem[NCTAS*MSLOTS*NTHREADS];

// ---------------------------------------------------------------------------
__global__ void wt_kernel(const float* __restrict__ w) {
    int i = blockIdx.x*256 + threadIdx.x;          // over co*ci*9
    if (i >= COUT_*CIN_*9) return;
    int co  = i / (CIN_*9);
    int rem = i - co*(CIN_*9);
    int ci  = rem / 9;
    int k   = rem - ci*9;
    g_wT[(k*CIN_ + ci)*COUT_ + co] = w[i];
}

// ---------------------------------------------------------------------------
// Packed fp32x2 helpers. Each lane of fma.rn.f32x2 rounds identically to
// scalar FFMA, so a packed chain == two independent scalar chains bitwise.
// ---------------------------------------------------------------------------
__device__ __forceinline__ void ffma2(u64 &d, u64 a, u64 b) {
    asm("fma.rn.f32x2 %0, %1, %2, %0;" : "+l"(d) : "l"(a), "l"(b));
}
__device__ __forceinline__ u64 pack2(float v) {   // {v, v}
    u64 r; asm("mov.b64 %0, {%1, %1};" : "=l"(r) : "f"(v)); return r;
}
__device__ __forceinline__ u64 packf(float a, float b) {   // {a, b}
    u64 r; asm("mov.b64 %0, {%1, %2};" : "=l"(r) : "f"(a), "f"(b)); return r;
}
__device__ __forceinline__ void unpack2(u64 v, float &lo, float &hi) {
    asm("mov.b64 {%0, %1}, %2;" : "=f"(lo), "=f"(hi) : "l"(v));
}

// pixel-packed step: 4 dup'd weights x pixel-pairs (P01={p0,p1}, P23={p2,p3})
// -> 8 FFMA2 into row R's accumulators acc2[R][cout][pair]
#define PSTEP(R, P01, P23)                                                     \
    do {                                                                       \
        ffma2(acc2[R][0][0], wd0, (P01)); ffma2(acc2[R][0][1], wd0, (P23));    \
        ffma2(acc2[R][1][0], wd1, (P01)); ffma2(acc2[R][1][1], wd1, (P23));    \
        ffma2(acc2[R][2][0], wd2, (P01)); ffma2(acc2[R][2][1], wd2, (P23));    \
        ffma2(acc2[R][3][0], wd3, (P01)); ffma2(acc2[R][3][1], wd3, (P23));    \
    } while (0)

#define LOAD_W(KWI)                                                            \
    float4 wq = *(const float4*)(wt + (KWI)*COUT_);                            \
    u64 wd0 = pack2(wq.x), wd1 = pack2(wq.y), wd2 = pack2(wq.z), wd3 = pack2(wq.w)

// ---------------------------------------------------------------------------
// Conv, reference-order chain k = (kh major, kw, ci minor); one fp32
// accumulator per output, packed as pixel-pairs per FFMA2 lane. 2-slot input
// ring (slot kh&1 = row oh0-1+kh); weights via gmem LDG (L2-resident,
// latency proven non-binding). Thread: 4 couts x 4 px x 2 rows.
// Membrane in global scratch (L2) -> smem 61.4KB -> 3 CTAs/SM.
// ---------------------------------------------------------------------------
__global__ __launch_bounds__(NTHREADS, 3)
void conv_spike_kernel(const float* __restrict__ x,
                       const float* __restrict__ cbias,
                       const float* __restrict__ gamma,
                       const float* __restrict__ beta,
                       const float* __restrict__ rmean,
                       const float* __restrict__ rvar,
                       const float* __restrict__ alpha,
                       float* __restrict__ out)
{
    extern __shared__ __align__(16) float s_in[];  // [2][128][60]

    const int oh0 = blockIdx.x * RPT;  // rows oh0, oh0+1
    const int ct  = blockIdx.y;        // 0..1
    const int b   = blockIdx.z;        // 0..15
    const int tid = threadIdx.x;       // 0..223
    const int cg  = tid & 15;          // cout group (fast across lanes)
    const int wg  = tid >> 4;          // width group 0..13
    const int ow0 = wg*PX;
    const int co0 = ct*CT + cg*CPT;
    const int ctaFlat = blockIdx.x + 28*(blockIdx.y + 2*blockIdx.z);
    float* mymem = g_mem + ctaFlat*MSLOTS*NTHREADS + tid;

    #pragma unroll 1
    for (int t = 0; t < T_; t++) {
        const float* xbt = x + (b*T_ + t)*CIN_*HW_;

        // fp32 accumulators: [row][cout][pixel-pair]  (lane lo = even pixel)
        u64 acc2[RPT][CPT][PX/2];
        #pragma unroll
        for (int r = 0; r < RPT; r++)
            #pragma unroll
            for (int c = 0; c < CPT; c++)
                #pragma unroll
                for (int j = 0; j < PX/2; j++) acc2[r][c][j] = 0ull;

        #pragma unroll 1
        for (int kh = 0; kh < 3; kh++) {
            const int sA = kh & 1;     // slot of row ihA = oh0-1+kh
            const int sB = sA ^ 1;     // slot of row ihB = oh0+kh

            __syncthreads();           // prior reads done before overwrite
            if (kh == 0) {
                // stage both rows: slot0 = oh0-1, slot1 = oh0
                #pragma unroll 1
                for (int idx = tid; idx < 2*CIN_*14; idx += NTHREADS) {
                    int s   = idx / (CIN_*14);
                    int rem = idx - s*(CIN_*14);
                    int ci  = rem / 14;
                    int g   = rem - ci*14;
                    int ih  = oh0 - 1 + s;
                    float* d = s_in + (s*CIN_ + ci)*SROW + 1 + g*4;
                    if ((unsigned)ih < (unsigned)H_) {
                        float4 v = *(const float4*)(xbt + ci*HW_ + ih*W_ + g*4);
                        d[0] = v.x; d[1] = v.y; d[2] = v.z; d[3] = v.w;
                    } else {
                        d[0] = 0.f; d[1] = 0.f; d[2] = 0.f; d[3] = 0.f;
                    }
                }
                #pragma unroll 1
                for (int sc = tid; sc < 2*CIN_; sc += NTHREADS) {
                    s_in[sc*SROW]      = 0.f;
                    s_in[sc*SROW + 57] = 0.f;
                }
            } else {
                // stage only the new row ihB = oh0+kh into slot sB
                const int ih = oh0 + kh;
                #pragma unroll 1
                for (int idx = tid; idx < CIN_*14; idx += NTHREADS) {
                    int ci = idx / 14;
                    int g  = idx - ci*14;
                    float* d = s_in + (sB*CIN_ + ci)*SROW + 1 + g*4;
                    if ((unsigned)ih < (unsigned)H_) {
                        float4 v = *(const float4*)(xbt + ci*HW_ + ih*W_ + g*4);
                        d[0] = v.x; d[1] = v.y; d[2] = v.z; d[3] = v.w;
                    } else {
                        d[0] = 0.f; d[1] = 0.f; d[2] = 0.f; d[3] = 0.f;
                    }
                }
                #pragma unroll 1
                for (int ci = tid; ci < CIN_; ci += NTHREADS) {
                    s_in[(sB*CIN_ + ci)*SROW]      = 0.f;
                    s_in[(sB*CIN_ + ci)*SROW + 57] = 0.f;
                }
            }
            __syncthreads();

            // chain: kw 0..2 in order, ci 0..127 inner (reference k-order)
            {   // kw = 0: window idx ow0..ow0+3 (16B-aligned) -> direct pairs
                const float* wt = g_wT + ((kh*3 + 0)*CIN_)*COUT_ + co0;
                const float* iA = s_in + sA*CIN_*SROW + ow0;
                const float* iB = s_in + sB*CIN_*SROW + ow0;
                #pragma unroll 4
                for (int ci = 0; ci < CIN_; ci++) {
                    LOAD_W(ci);
                    ulonglong2 va = *(const ulonglong2*)(iA + ci*SROW);
                    ulonglong2 vb = *(const ulonglong2*)(iB + ci*SROW);
                    PSTEP(0, va.x, va.y);
                    PSTEP(1, vb.x, vb.y);
                }
            }
            {   // kw = 1: window idx ow0+1..ow0+4 -> quad + scalar, 2 packf/row
                const float* wt = g_wT + ((kh*3 + 1)*CIN_)*COUT_ + co0;
                const float* iA = s_in + sA*CIN_*SROW + ow0;
                const float* iB = s_in + sB*CIN_*SROW + ow0;
                #pragma unroll 4
                for (int ci = 0; ci < CIN_; ci++) {
                    LOAD_W(ci);
                    float4 qa = *(const float4*)(iA + ci*SROW);
                    float  a4 = iA[ci*SROW + 4];
                    float4 qb = *(const float4*)(iB + ci*SROW);
                    float  b4 = iB[ci*SROW + 4];
                    PSTEP(0, packf(qa.y, qa.z), packf(qa.w, a4));
                    PSTEP(1, packf(qb.y, qb.z), packf(qb.w, b4));
                }
            }
            {   // kw = 2: window idx ow0+2..ow0+5 (8B-aligned) -> direct pairs
                const float* wt = g_wT + ((kh*3 + 2)*CIN_)*COUT_ + co0;
                const float* iA = s_in + sA*CIN_*SROW + ow0 + 2;
                const float* iB = s_in + sB*CIN_*SROW + ow0 + 2;
                #pragma unroll 4
                for (int ci = 0; ci < CIN_; ci++) {
                    LOAD_W(ci);
                    u64 a01 = *(const u64*)(iA + ci*SROW);
                    u64 a23 = *(const u64*)(iA + ci*SROW + 2);
                    u64 b01 = *(const u64*)(iB + ci*SROW);
                    u64 b23 = *(const u64*)(iB + ci*SROW + 2);
                    PSTEP(0, a01, a23);
                    PSTEP(1, b01, b23);
                }
            }
        }

        // --- per-timestep epilogue: replicate reference fp32 roundings ---
        const float tscale = (float)(1 << (3 - t));   // exact power of 2
        #pragma unroll 1
        for (int c = 0; c < CPT; c++) {
            int co = co0 + c;
            float cb = cbias[co];
            float mn = rmean[co];
            float iv = __fmul_rn(__fdiv_rn(1.0f, __fsqrt_rn(__fadd_rn(rvar[co], 1e-5f))),
                                 gamma[co]);
            float bt = beta[co];
            #pragma unroll
            for (int r = 0; r < RPT; r++) {
                #pragma unroll
                for (int j = 0; j < PX/2; j++) {
                    float plo, phi;
                    unpack2(acc2[r][c][j], plo, phi);
                    #pragma unroll
                    for (int half = 0; half < 2; half++) {
                        float y = half ? phi : plo;                // raw conv acc
                        y = __fadd_rn(y, cb);                      // + bias
                        y = __fmul_rn(y, 1.875f);                  // * 15/8
                        y = __fmul_rn(__fsub_rn(y, mn), iv);       // BN sub, mul
                        y = __fadd_rn(y, bt);                      // + beta
                        y = __fdiv_rn(y, 15.0f);                   // / 15
                        float prod = __fmul_rn(y, tscale);         // exact
                        int p  = 2*j + half;
                        int mi = ((r*CPT + c)*PX + p)*NTHREADS;    // coalesced
                        mymem[mi] = (t == 0) ? prod : __fadd_rn(mymem[mi], prod);
                    }
                }
            }
        }
    }

    // ----- spike scan (identical fp32 ops to reference) -----
    const float thr = __fdiv_rn(__fmul_rn(*alpha, 8.0f), 15.0f);
    const float coef[4] = {0.9375f, 0.875f, 0.75f, 0.5f};

    #pragma unroll 1
    for (int r = 0; r < RPT; r++) {
        #pragma unroll 1
        for (int c = 0; c < CPT; c++) {
            int co = co0 + c;
            float mem[PX];
            #pragma unroll
            for (int p = 0; p < PX; p++)
                mem[p] = mymem[((r*CPT + c)*PX + p)*NTHREADS];
            float* obase = out + (b*T_*COUT_ + co)*HW_ + (oh0 + r)*W_ + ow0;
            #pragma unroll
            for (int dt = 0; dt < 4; dt++) {
                float cthr = __fmul_rn(coef[dt], thr);
                float4 o;
                float s0 = (mem[0] >= cthr) ? thr : 0.f; mem[0] = __fmul_rn(__fsub_rn(mem[0], s0), 2.f);
                float s1 = (mem[1] >= cthr) ? thr : 0.f; mem[1] = __fmul_rn(__fsub_rn(mem[1], s1), 2.f);
                float s2 = (mem[2] >= cthr) ? thr : 0.f; mem[2] = __fmul_rn(__fsub_rn(mem[2], s2), 2.f);
                float s3 = (mem[3] >= cthr) ? thr : 0.f; mem[3] = __fmul_rn(__fsub_rn(mem[3], s3), 2.f);
                o.x = s0; o.y = s1; o.z = s2; o.w = s3;
                *(float4*)(obase + dt*COUT_*HW_) = o;
            }
        }
    }
}

// ---------------------------------------------------------------------------
extern "C" void kernel_launch(void* const* d_in, const int* in_sizes, int n_in,
                              void* d_out, int out_size) {
    const float* x     = (const float*)d_in[0];
    const float* convw = (const float*)d_in[1];
    const float* convb = (const float*)d_in[2];
    const float* gamma = (const float*)d_in[3];
    const float* beta  = (const float*)d_in[4];
    const float* rmean = (const float*)d_in[5];
    const float* rvar  = (const float*)d_in[6];
    const float* alpha = (const float*)d_in[7];
    float* out = (float*)d_out;

    cudaFuncSetAttribute(conv_spike_kernel,
                         cudaFuncAttributeMaxDynamicSharedMemorySize,
                         SMEM_BYTES);

    wt_kernel<<<(COUT_*CIN_*9 + 255)/256, 256>>>(convw);

    dim3 grid(H_/RPT, COUT_/CT, B_);   // 28 x 2 x 16 = 896 CTAs
    conv_spike_kernel<<<grid, NTHREADS, SMEM_BYTES>>>(x, convb, gamma, beta,
                                                      rmean, rvar, alpha, out);
}

// round 17
// speedup vs baseline: 1.1688x; 1.1688x over previous
#include <cuda_runtime.h>
#include <math.h>

#define B_    16
#define T_    4
#define CIN_  128
#define COUT_ 128
#define H_    56
#define W_    56
#define HW_   (H_*W_)

#define CT    64     // couts per block
#define CPT   4      // couts per thread
#define PX    4      // pixels per thread
#define RPT   2      // output rows per thread (share weight loads)
#define NTHREADS 224 // cg = tid&15 (16 cout-groups), wg = tid>>4 (14 width-groups)
#define NCTAS (28*2*16)                // 896
#define MSLOTS (RPT*CPT*PX)            // 32 membrane slots per thread

// weight eighth-tiles: 16 ci x 64 co, double-buffered
#define WT_E  16
#define WBUF  (WT_E*CT)                // 1024 floats = 4KB

// dynamic smem: s_in[2][128][60] ring + s_w[2][WBUF]
#define SROW   60
#define WOFF   (2*CIN_*SROW)
#define SMEM_BYTES ((WOFF + 2*WBUF)*4) // 61440 + 8192 = 69632 -> 3 CTAs/SM

typedef unsigned long long u64;

// transposed weights: wT[kh][kw][ci][co]
__device__ float g_wT[9*CIN_*COUT_];
// membrane scratch: [cta][slot][tid] — coalesced per slot, L2-resident
__device__ float g_mem[NCTAS*MSLOTS*NTHREADS];

// ---------------------------------------------------------------------------
__global__ void wt_kernel(const float* __restrict__ w) {
    int i = blockIdx.x*256 + threadIdx.x;          // over co*ci*9
    if (i >= COUT_*CIN_*9) return;
    int co  = i / (CIN_*9);
    int rem = i - co*(CIN_*9);
    int ci  = rem / 9;
    int k   = rem - ci*9;
    g_wT[(k*CIN_ + ci)*COUT_ + co] = w[i];
}

// ---------------------------------------------------------------------------
// Packed fp32x2 helpers. Each lane of fma.rn.f32x2 rounds identically to
// scalar FFMA, so a packed chain == two independent scalar chains bitwise.
// ---------------------------------------------------------------------------
__device__ __forceinline__ void ffma2(u64 &d, u64 a, u64 b) {
    asm("fma.rn.f32x2 %0, %1, %2, %0;" : "+l"(d) : "l"(a), "l"(b));
}
__device__ __forceinline__ u64 pack2(float v) {   // {v, v}
    u64 r; asm("mov.b64 %0, {%1, %1};" : "=l"(r) : "f"(v)); return r;
}
__device__ __forceinline__ void unpack2(u64 v, float &lo, float &hi) {
    asm("mov.b64 {%0, %1}, %2;" : "=f"(lo), "=f"(hi) : "l"(v));
}

// weight pair WP x 4 dup'd inputs -> 8 FFMA2 into row R's accumulators
#define ROW_STEP(R, WP, I0, I1, I2, I3)                                         \
    do {                                                                        \
        ffma2(acc2[R][0][0], (WP).x, (I0)); ffma2(acc2[R][1][0], (WP).y, (I0)); \
        ffma2(acc2[R][0][1], (WP).x, (I1)); ffma2(acc2[R][1][1], (WP).y, (I1)); \
        ffma2(acc2[R][0][2], (WP).x, (I2)); ffma2(acc2[R][1][2], (WP).y, (I2)); \
        ffma2(acc2[R][0][3], (WP).x, (I3)); ffma2(acc2[R][1][3], (WP).y, (I3)); \
    } while (0)

// kw-specific bodies (rowA from iA, rowB from iB), same as the 1493 winner
#define BODY_KW0(WP, CI)                                                        \
    do {                                                                        \
        float4 a  = *(const float4*)(iA + (CI)*SROW);                           \
        float4 bb = *(const float4*)(iB + (CI)*SROW);                           \
        ROW_STEP(0, WP, pack2(a.x), pack2(a.y), pack2(a.z), pack2(a.w));        \
        ROW_STEP(1, WP, pack2(bb.x), pack2(bb.y), pack2(bb.z), pack2(bb.w));    \
    } while (0)
#define BODY_KW1(WP, CI)                                                        \
    do {                                                                        \
        float4 a  = *(const float4*)(iA + (CI)*SROW);                           \
        float  a4 = iA[(CI)*SROW + 4];                                          \
        float4 bb = *(const float4*)(iB + (CI)*SROW);                           \
        float  b4 = iB[(CI)*SROW + 4];                                          \
        ROW_STEP(0, WP, pack2(a.y), pack2(a.z), pack2(a.w), pack2(a4));         \
        ROW_STEP(1, WP, pack2(bb.y), pack2(bb.z), pack2(bb.w), pack2(b4));      \
    } while (0)
#define BODY_KW2(WP, CI)                                                        \
    do {                                                                        \
        float2 a01 = *(const float2*)(iA + (CI)*SROW);                          \
        float2 a23 = *(const float2*)(iA + (CI)*SROW + 2);                      \
        float2 b01 = *(const float2*)(iB + (CI)*SROW);                          \
        float2 b23 = *(const float2*)(iB + (CI)*SROW + 2);                      \
        ROW_STEP(0, WP, pack2(a01.x), pack2(a01.y), pack2(a23.x), pack2(a23.y));\
        ROW_STEP(1, WP, pack2(b01.x), pack2(b01.y), pack2(b23.x), pack2(b23.y));\
    } while (0)

// stage weight eighth E (ci rows E*16..E*16+15, all 64 couts) into buffer BUF
#define STAGE_W(E, BUF)                                                         \
    do {                                                                        \
        _Pragma("unroll 1")                                                     \
        for (int ii = tid; ii < WT_E*CT/4; ii += NTHREADS) {                    \
            int ci_l = ii >> 4;                                                 \
            int c4   = (ii & 15) << 2;                                          \
            *(float4*)(s_w + (BUF)*WBUF + ci_l*CT + c4) =                       \
                *(const float4*)(wsrc + ((E)*WT_E + ci_l)*COUT_ + c4);          \
        }                                                                       \
    } while (0)

// ping-pong pipeline over eighths: stage e+1 while computing e; ci ascending
#define KW_PIPE(BODY)                                                           \
    do {                                                                        \
        STAGE_W(0, 0);                                                          \
        __syncthreads();                                                        \
        _Pragma("unroll 1")                                                     \
        for (int e = 0; e < 8; e++) {                                           \
            if (e < 7) STAGE_W(e+1, (e+1)&1);                                   \
            const float* wte = s_w + (e&1)*WBUF + cg*CPT;                       \
            _Pragma("unroll 4")                                                 \
            for (int cl = 0; cl < WT_E; cl++) {                                 \
                ulonglong2 wp = *(const ulonglong2*)(wte + cl*CT);              \
                int ci = e*WT_E + cl;                                           \
                BODY(wp, ci);                                                   \
            }                                                                   \
            __syncthreads();                                                    \
        }                                                                       \
    } while (0)

// ---------------------------------------------------------------------------
// Conv, reference-order chain k = (kh major, kw, ci minor); one fp32
// accumulator per output (packed in cout-pairs). 2-slot input ring; weights
// staged per-tap in 4KB eighth-tiles (ping-pong, CTA-shared LDS reads).
// Thread: 4 couts x 4 px x 2 rows. Membrane in global scratch (L2).
// ---------------------------------------------------------------------------
__global__ __launch_bounds__(NTHREADS, 3)
void conv_spike_kernel(const float* __restrict__ x,
                       const float* __restrict__ cbias,
                       const float* __restrict__ gamma,
                       const float* __restrict__ beta,
                       const float* __restrict__ rmean,
                       const float* __restrict__ rvar,
                       const float* __restrict__ alpha,
                       float* __restrict__ out)
{
    extern __shared__ __align__(16) float s_in[];  // [2][128][60] + s_w
    float* s_w = s_in + WOFF;                      // [2][WBUF]

    const int oh0 = blockIdx.x * RPT;  // rows oh0, oh0+1
    const int ct  = blockIdx.y;        // 0..1
    const int b   = blockIdx.z;        // 0..15
    const int tid = threadIdx.x;       // 0..223
    const int cg  = tid & 15;          // cout group (fast across lanes)
    const int wg  = tid >> 4;          // width group 0..13
    const int ow0 = wg*PX;
    const int co0 = ct*CT + cg*CPT;
    const int ctaFlat = blockIdx.x + 28*(blockIdx.y + 2*blockIdx.z);
    float* mymem = g_mem + ctaFlat*MSLOTS*NTHREADS + tid;

    #pragma unroll 1
    for (int t = 0; t < T_; t++) {
        const float* xbt = x + (b*T_ + t)*CIN_*HW_;

        // fp32 accumulators: [row][cout-pair][pixel]
        u64 acc2[RPT][CPT/2][PX];
        #pragma unroll
        for (int r = 0; r < RPT; r++)
            #pragma unroll
            for (int q = 0; q < CPT/2; q++)
                #pragma unroll
                for (int p = 0; p < PX; p++) acc2[r][q][p] = 0ull;

        #pragma unroll 1
        for (int kh = 0; kh < 3; kh++) {
            const int sA = kh & 1;     // slot of row ihA = oh0-1+kh
            const int sB = sA ^ 1;     // slot of row ihB = oh0+kh

            // ---- stage input rows for this kh (prior tap ended with sync) ----
            if (kh == 0) {
                #pragma unroll 1
                for (int idx = tid; idx < 2*CIN_*14; idx += NTHREADS) {
                    int s   = idx / (CIN_*14);
                    int rem = idx - s*(CIN_*14);
                    int ci  = rem / 14;
                    int g   = rem - ci*14;
                    int ih  = oh0 - 1 + s;
                    float* d = s_in + (s*CIN_ + ci)*SROW + 1 + g*4;
                    if ((unsigned)ih < (unsigned)H_) {
                        float4 v = *(const float4*)(xbt + ci*HW_ + ih*W_ + g*4);
                        d[0] = v.x; d[1] = v.y; d[2] = v.z; d[3] = v.w;
                    } else {
                        d[0] = 0.f; d[1] = 0.f; d[2] = 0.f; d[3] = 0.f;
                    }
                }
                #pragma unroll 1
                for (int sc = tid; sc < 2*CIN_; sc += NTHREADS) {
                    s_in[sc*SROW]      = 0.f;
                    s_in[sc*SROW + 57] = 0.f;
                }
            } else {
                const int ih = oh0 + kh;
                #pragma unroll 1
                for (int idx = tid; idx < CIN_*14; idx += NTHREADS) {
                    int ci = idx / 14;
                    int g  = idx - ci*14;
                    float* d = s_in + (sB*CIN_ + ci)*SROW + 1 + g*4;
                    if ((unsigned)ih < (unsigned)H_) {
                        float4 v = *(const float4*)(xbt + ci*HW_ + ih*W_ + g*4);
                        d[0] = v.x; d[1] = v.y; d[2] = v.z; d[3] = v.w;
                    } else {
                        d[0] = 0.f; d[1] = 0.f; d[2] = 0.f; d[3] = 0.f;
                    }
                }
                #pragma unroll 1
                for (int ci = tid; ci < CIN_; ci += NTHREADS) {
                    s_in[(sB*CIN_ + ci)*SROW]      = 0.f;
                    s_in[(sB*CIN_ + ci)*SROW + 57] = 0.f;
                }
            }
            // (visibility of rows ensured by the sync inside KW_PIPE)

            // chain: kw 0..2 in order, ci 0..127 inner (reference k-order)
            {   // kw = 0: window idx ow0..ow0+3 (16B-aligned)
                const float* wsrc = g_wT + ((kh*3 + 0)*CIN_)*COUT_ + ct*CT;
                const float* iA = s_in + sA*CIN_*SROW + ow0;
                const float* iB = s_in + sB*CIN_*SROW + ow0;
                KW_PIPE(BODY_KW0);
            }
            {   // kw = 1: window idx ow0+1..ow0+4
                const float* wsrc = g_wT + ((kh*3 + 1)*CIN_)*COUT_ + ct*CT;
                const float* iA = s_in + sA*CIN_*SROW + ow0;
                const float* iB = s_in + sB*CIN_*SROW + ow0;
                KW_PIPE(BODY_KW1);
            }
            {   // kw = 2: window idx ow0+2..ow0+5 (8B-aligned)
                const float* wsrc = g_wT + ((kh*3 + 2)*CIN_)*COUT_ + ct*CT;
                const float* iA = s_in + sA*CIN_*SROW + ow0 + 2;
                const float* iB = s_in + sB*CIN_*SROW + ow0 + 2;
                KW_PIPE(BODY_KW2);
            }
        }

        // --- per-timestep epilogue: replicate reference fp32 roundings ---
        const float tscale = (float)(1 << (3 - t));   // exact power of 2
        #pragma unroll 1
        for (int c = 0; c < CPT; c++) {
            int co = co0 + c;
            float cb = cbias[co];
            float mn = rmean[co];
            float iv = __fmul_rn(__fdiv_rn(1.0f, __fsqrt_rn(__fadd_rn(rvar[co], 1e-5f))),
                                 gamma[co]);
            float bt = beta[co];
            int q = c >> 1, half = c & 1;
            #pragma unroll
            for (int r = 0; r < RPT; r++) {
                #pragma unroll
                for (int p = 0; p < PX; p++) {
                    float al, ah;
                    unpack2(acc2[r][q][p], al, ah);
                    float y = half ? ah : al;                  // raw conv accumulator
                    y = __fadd_rn(y, cb);                      // + bias
                    y = __fmul_rn(y, 1.875f);                  // * (2^T-1)/2^(T-1)
                    y = __fmul_rn(__fsub_rn(y, mn), iv);       // BN sub, mul
                    y = __fadd_rn(y, bt);                      // + beta
                    y = __fdiv_rn(y, 15.0f);                   // / (2^T-1)
                    float prod = __fmul_rn(y, tscale);         // exact (power of 2)
                    int mi = ((r*CPT + c)*PX + p)*NTHREADS;    // coalesced slot
                    mymem[mi] = (t == 0) ? prod : __fadd_rn(mymem[mi], prod);
                }
            }
        }
    }

    // ----- spike scan (identical fp32 ops to reference) -----
    const float thr = __fdiv_rn(__fmul_rn(*alpha, 8.0f), 15.0f);
    const float coef[4] = {0.9375f, 0.875f, 0.75f, 0.5f};

    #pragma unroll 1
    for (int r = 0; r < RPT; r++) {
        #pragma unroll 1
        for (int c = 0; c < CPT; c++) {
            int co = co0 + c;
            float mem[PX];
            #pragma unroll
            for (int p = 0; p < PX; p++)
                mem[p] = mymem[((r*CPT + c)*PX + p)*NTHREADS];
            float* obase = out + (b*T_*COUT_ + co)*HW_ + (oh0 + r)*W_ + ow0;
            #pragma unroll
            for (int dt = 0; dt < 4; dt++) {
                float cthr = __fmul_rn(coef[dt], thr);
                float4 o;
                float s0 = (mem[0] >= cthr) ? thr : 0.f; mem[0] = __fmul_rn(__fsub_rn(mem[0], s0), 2.f);
                float s1 = (mem[1] >= cthr) ? thr : 0.f; mem[1] = __fmul_rn(__fsub_rn(mem[1], s1), 2.f);
                float s2 = (mem[2] >= cthr) ? thr : 0.f; mem[2] = __fmul_rn(__fsub_rn(mem[2], s2), 2.f);
                float s3 = (mem[3] >= cthr) ? thr : 0.f; mem[3] = __fmul_rn(__fsub_rn(mem[3], s3), 2.f);
                o.x = s0; o.y = s1; o.z = s2; o.w = s3;
                *(float4*)(obase + dt*COUT_*HW_) = o;
            }
        }
    }
}

// ---------------------------------------------------------------------------
extern "C" void kernel_launch(void* const* d_in, const int* in_sizes, int n_in,
                              void* d_out, int out_size) {
    const float* x     = (const float*)d_in[0];
    const float* convw = (const float*)d_in[1];
    const float* convb = (const float*)d_in[2];
    const float* gamma = (const float*)d_in[3];
    const float* beta  = (const float*)d_in[4];
    const float* rmean = (const float*)d_in[5];
    const float* rvar  = (const float*)d_in[6];
    const float* alpha = (const float*)d_in[7];
    float* out = (float*)d_out;

    cudaFuncSetAttribute(conv_spike_kernel,
                         cudaFuncAttributeMaxDynamicSharedMemorySize,
                         SMEM_BYTES);

    wt_kernel<<<(COUT_*CIN_*9 + 255)/256, 256>>>(convw);

    dim3 grid(H_/RPT, COUT_/CT, B_);   // 28 x 2 x 16 = 896 CTAs
    conv_spike_kernel<<<grid, NTHREADS, SMEM_BYTES>>>(x, convb, gamma, beta,
                                                      rmean, rvar, alpha, out);
}